// round 6
// baseline (speedup 1.0000x reference)
#include <cuda_runtime.h>
#include <cuda_bf16.h>
#include <cstdint>
#include <math.h>

// ===================== constants =====================
#define BMAX   4096
#define DMAX   2048
#define BM 128
#define BN 128
#define TBK 64                      // bf16 K per chunk = 128 bytes/row
#define STAGES 3
#define A_BYTES (BM*TBK*2)          // 16384
#define B_BYTES (BN*TBK*2)          // 16384
#define STAGE_BYTES (A_BYTES+B_BYTES)   // 32768
#define META_OFF (STAGES*STAGE_BYTES)   // 98304 (labels/sq, 2 KB)
#define SMEM_TOTAL (META_OFF + 2048)    // 100352 -> 2 CTAs/SM
#define NCHUNK (BMAX/BN)            // 32

// ===================== device scratch =====================
__device__ __nv_bfloat16 g_ebf[(size_t)BMAX * DMAX];
__device__ float g_sq[BMAX];
__device__ float g_posV[NCHUNK][BMAX];
__device__ int   g_posI[NCHUNK][BMAX];
__device__ float g_negV[NCHUNK][BMAX];
__device__ int   g_negI[NCHUNK][BMAX];
__device__ int   g_valid[BMAX];
__device__ float g_loss[BMAX];
__device__ int   g_ticket;

// ===================== helpers =====================
__device__ __forceinline__ uint32_t smem_u32(const void* p) {
    uint32_t a;
    asm("{ .reg .u64 t; cvta.to.shared.u64 t, %1; cvt.u32.u64 %0, t; }" : "=r"(a) : "l"(p));
    return a;
}
__device__ __forceinline__ void cpa16(uint32_t s, const void* g) {
    asm volatile("cp.async.cg.shared.global [%0], [%1], 16;" :: "r"(s), "l"(g));
}
#define CPA_COMMIT() asm volatile("cp.async.commit_group;" ::: "memory")
#define CPA_WAIT(N)  asm volatile("cp.async.wait_group %0;" :: "n"(N) : "memory")

__device__ __forceinline__ void ldsm4(uint32_t* r, uint32_t addr) {
    asm volatile("ldmatrix.sync.aligned.m8n8.x4.shared.b16 {%0,%1,%2,%3}, [%4];"
                 : "=r"(r[0]), "=r"(r[1]), "=r"(r[2]), "=r"(r[3]) : "r"(addr));
}
__device__ __forceinline__ void mma16816(float* c, const uint32_t* a, const uint32_t* b) {
    asm volatile(
        "mma.sync.aligned.m16n8k16.row.col.f32.bf16.bf16.f32 "
        "{%0,%1,%2,%3}, {%4,%5,%6,%7}, {%8,%9}, {%0,%1,%2,%3};"
        : "+f"(c[0]), "+f"(c[1]), "+f"(c[2]), "+f"(c[3])
        : "r"(a[0]), "r"(a[1]), "r"(a[2]), "r"(a[3]), "r"(b[0]), "r"(b[1]));
}

__device__ __forceinline__ void selMax(float& v, int& i, float nv, int ni) {
    if (nv > v || (nv == v && ni < i)) { v = nv; i = ni; }
}
__device__ __forceinline__ void selMin(float& v, int& i, float nv, int ni) {
    if (nv < v || (nv == v && ni < i)) { v = nv; i = ni; }
}

// ===================== kernel 1: fp32 -> bf16 + row sumsq (+ticket reset) ==========
__global__ void convKernel(const float* __restrict__ emb, int D) {
    if (blockIdx.x == 0 && threadIdx.x == 0) g_ticket = 0;

    // 2 rows per block
    for (int rr = 0; rr < 2; rr++) {
        int i = blockIdx.x * 2 + rr;
        const float4* row = reinterpret_cast<const float4*>(emb + (size_t)i * D);
        __nv_bfloat162* orow = reinterpret_cast<__nv_bfloat162*>(g_ebf + (size_t)i * D);
        float s = 0.f;
        for (int k = threadIdx.x; k < D / 4; k += blockDim.x) {
            float4 v = row[k];
            s += v.x * v.x + v.y * v.y + v.z * v.z + v.w * v.w;
            __nv_bfloat162 h0, h1;
            h0.x = __float2bfloat16(v.x); h0.y = __float2bfloat16(v.y);
            h1.x = __float2bfloat16(v.z); h1.y = __float2bfloat16(v.w);
            orow[2 * k] = h0; orow[2 * k + 1] = h1;
        }
        for (int off = 16; off > 0; off >>= 1)
            s += __shfl_down_sync(0xFFFFFFFFu, s, off);
        __shared__ float ws[8];
        if ((threadIdx.x & 31) == 0) ws[threadIdx.x >> 5] = s;
        __syncthreads();
        if (threadIdx.x == 0) {
            float t = 0.f;
            for (int w = 0; w < (int)(blockDim.x >> 5); w++) t += ws[w];
            g_sq[i] = t;
        }
        __syncthreads();
    }
}

// ===================== kernel 2: bf16 HMMA GEMM (upper triangle) + dual selection ==========
__device__ __forceinline__ void load_chunk(int tid, uint32_t sbase, int s,
                                           int iBase, int jBase, int c, int D) {
    uint32_t sA = sbase + s * STAGE_BYTES;
    uint32_t sB = sA + A_BYTES;
    int k0 = c * TBK;
    const char* gA = (const char*)(g_ebf + (size_t)iBase * D + k0);
    const char* gB = (const char*)(g_ebf + (size_t)jBase * D + k0);
#pragma unroll
    for (int t = 0; t < 4; t++) {
        int f = tid + t * 256;
        int row = f >> 3, c16 = f & 7;
        int colb = c16 * 16;
        uint32_t off = (uint32_t)(row * 128 + (colb ^ ((row & 7) << 4)));
        cpa16(sA + off, gA + (size_t)row * (size_t)(D * 2) + colb);
    }
#pragma unroll
    for (int t = 0; t < 4; t++) {
        int f = tid + t * 256;
        int row = f >> 3, c16 = f & 7;
        int colb = c16 * 16;
        uint32_t off = (uint32_t)(row * 128 + (colb ^ ((row & 7) << 4)));
        cpa16(sB + off, gB + (size_t)row * (size_t)(D * 2) + colb);
    }
    CPA_COMMIT();
}

__global__ __launch_bounds__(256, 2) void distKernel(const int* __restrict__ labels,
                                                     int B, int D) {
    extern __shared__ char sm[];
    uint32_t sbase = smem_u32(sm);

    const int tid  = threadIdx.x;
    const int wid  = tid >> 5;
    const int lane = tid & 31;
    const int warpM = wid & 1;       // 0..1 (64 rows each)
    const int warpN = wid >> 1;      // 0..3 (32 cols each)

    // decode upper-triangular tile (bi <= bj)
    const int nb = B / BM;           // 32
    int bi = 0, rem = blockIdx.x;
    while (rem >= nb - bi) { rem -= nb - bi; bi++; }
    const int bj = bi + rem;
    const int iBase = bi * BM;
    const int jBase = bj * BN;
    const bool diag = (bi == bj);

    int*   sLabJ = (int*)  (sm + META_OFF);
    float* sSqJ  = (float*)(sm + META_OFF + 512);
    int*   sLabI = (int*)  (sm + META_OFF + 1024);
    float* sSqI  = (float*)(sm + META_OFF + 1536);
    float* sPosV  = (float*)(sm);
    int*   sPosI  = (int*)  (sm + 2048);
    float* sNegV  = (float*)(sm + 4096);
    int*   sNegI  = (int*)  (sm + 6144);
    float* sPosVc = (float*)(sm + 8192);
    int*   sPosIc = (int*)  (sm + 9216);
    float* sNegVc = (float*)(sm + 10240);
    int*   sNegIc = (int*)  (sm + 11264);

    if (tid < 128) {
        sLabJ[tid] = labels[jBase + tid];
        sSqJ[tid]  = g_sq[jBase + tid];
        sLabI[tid] = labels[iBase + tid];
        sSqI[tid]  = g_sq[iBase + tid];
    }

    const int rowA_l = (lane & 7) + ((lane >> 3) & 1) * 8;
    const int colA_b = (lane >> 4) * 16;
    const int rowB_l = (lane & 7) + (lane >> 4) * 8;
    const int colB_b = ((lane >> 3) & 1) * 16;

    int aRow[4], bRow[2];
#pragma unroll
    for (int mf = 0; mf < 4; mf++) aRow[mf] = warpM * 64 + mf * 16 + rowA_l;
#pragma unroll
    for (int nf = 0; nf < 2; nf++) bRow[nf] = warpN * 32 + nf * 16 + rowB_l;

    float acc[4][4][4];
#pragma unroll
    for (int a = 0; a < 4; a++)
#pragma unroll
        for (int b = 0; b < 4; b++)
#pragma unroll
            for (int c = 0; c < 4; c++) acc[a][b][c] = 0.f;

    const int nch = D / TBK;     // 32

    load_chunk(tid, sbase, 0, iBase, jBase, 0, D);
    load_chunk(tid, sbase, 1, iBase, jBase, 1, D);

    for (int c = 0; c < nch; c++) {
        if (c == nch - 1) { CPA_WAIT(0); } else { CPA_WAIT(1); }
        __syncthreads();
        if (c + 2 < nch)
            load_chunk(tid, sbase, (c + 2) % STAGES, iBase, jBase, c + 2, D);

        uint32_t sA = sbase + (c % STAGES) * STAGE_BYTES;
        uint32_t sB = sA + A_BYTES;
#pragma unroll
        for (int ks = 0; ks < TBK / 16; ks++) {
            uint32_t aF[16], bF[8];
#pragma unroll
            for (int mf = 0; mf < 4; mf++) {
                int r = aRow[mf];
                uint32_t addr = sA + r * 128 + ((ks * 32 + colA_b) ^ ((r & 7) << 4));
                ldsm4(aF + mf * 4, addr);
            }
#pragma unroll
            for (int nf = 0; nf < 2; nf++) {
                int r = bRow[nf];
                uint32_t addr = sB + r * 128 + ((ks * 32 + colB_b) ^ ((r & 7) << 4));
                ldsm4(bF + nf * 4, addr);
            }
#pragma unroll
            for (int mf = 0; mf < 4; mf++)
#pragma unroll
                for (int n8 = 0; n8 < 4; n8++)
                    mma16816(acc[mf][n8], aF + mf * 4, bF + n8 * 2);
        }
    }
    __syncthreads();

    // ---- epilogue: d^2 + dual hard pos/neg selection ----
    const int g = lane >> 2;
    const int q = lane & 3;

    int   jLab[8];
    float jSq[8];
    int   jIdx[8];
#pragma unroll
    for (int n8 = 0; n8 < 4; n8++)
#pragma unroll
        for (int cc = 0; cc < 2; cc++) {
            int jj = warpN * 32 + n8 * 8 + q * 2 + cc;
            jLab[n8 * 2 + cc] = sLabJ[jj];
            jSq[n8 * 2 + cc]  = sSqJ[jj];
            jIdx[n8 * 2 + cc] = jBase + jj;
        }

    float cpV[8], cnV[8];
    int   cpI[8], cnI[8];
#pragma unroll
    for (int t = 0; t < 8; t++) {
        cpV[t] = -1.f; cpI[t] = 1 << 30;
        cnV[t] = 3.4e38f; cnI[t] = 1 << 30;
    }

#pragma unroll
    for (int mf = 0; mf < 4; mf++) {
#pragma unroll
        for (int h = 0; h < 2; h++) {
            int rl   = warpM * 64 + mf * 16 + h * 8 + g;
            int iRow = iBase + rl;
            float sqi = sSqI[rl];
            int   lab = sLabI[rl];
            float bpV = -1.f, bnV = 3.4e38f;
            int   bpI = 1 << 30, bnI = 1 << 30;
#pragma unroll
            for (int t = 0; t < 8; t++) {
                int n8 = t >> 1, cc = t & 1;
                int j = jIdx[t];
                float dot = acc[mf][n8][h * 2 + cc];
                float d2 = fmaxf(sqi + jSq[t] - 2.f * dot, 0.f);
                if (jLab[t] == lab) {
                    if (j != iRow) {
                        selMax(bpV, bpI, d2, j);
                        selMax(cpV[t], cpI[t], d2, iRow);
                    }
                } else {
                    selMin(bnV, bnI, d2, j);
                    selMin(cnV[t], cnI[t], d2, iRow);
                }
            }
#pragma unroll
            for (int off = 1; off <= 2; off <<= 1) {
                float pv = __shfl_xor_sync(0xFFFFFFFFu, bpV, off);
                int   pi = __shfl_xor_sync(0xFFFFFFFFu, bpI, off);
                selMax(bpV, bpI, pv, pi);
                float nv = __shfl_xor_sync(0xFFFFFFFFu, bnV, off);
                int   ni = __shfl_xor_sync(0xFFFFFFFFu, bnI, off);
                selMin(bnV, bnI, nv, ni);
            }
            if (q == 0) {
                sPosV[rl * 4 + warpN] = bpV;
                sPosI[rl * 4 + warpN] = bpI;
                sNegV[rl * 4 + warpN] = bnV;
                sNegI[rl * 4 + warpN] = bnI;
            }
        }
    }

    if (!diag) {
#pragma unroll
        for (int t = 0; t < 8; t++) {
#pragma unroll
            for (int off = 4; off <= 16; off <<= 1) {
                float pv = __shfl_xor_sync(0xFFFFFFFFu, cpV[t], off);
                int   pi = __shfl_xor_sync(0xFFFFFFFFu, cpI[t], off);
                selMax(cpV[t], cpI[t], pv, pi);
                float nv = __shfl_xor_sync(0xFFFFFFFFu, cnV[t], off);
                int   ni = __shfl_xor_sync(0xFFFFFFFFu, cnI[t], off);
                selMin(cnV[t], cnI[t], nv, ni);
            }
        }
        if (g == 0) {
#pragma unroll
            for (int t = 0; t < 8; t++) {
                int n8 = t >> 1, cc = t & 1;
                int jj = warpN * 32 + n8 * 8 + q * 2 + cc;
                sPosVc[jj * 2 + warpM] = cpV[t];
                sPosIc[jj * 2 + warpM] = cpI[t];
                sNegVc[jj * 2 + warpM] = cnV[t];
                sNegIc[jj * 2 + warpM] = cnI[t];
            }
        }
    }
    __syncthreads();

    if (tid < 128) {
        float bpV = -2.f, bnV = 3.5e38f;
        int bpI = 1 << 30, bnI = 1 << 30;
#pragma unroll
        for (int wn = 0; wn < 4; wn++) {
            selMax(bpV, bpI, sPosV[tid * 4 + wn], sPosI[tid * 4 + wn]);
            selMin(bnV, bnI, sNegV[tid * 4 + wn], sNegI[tid * 4 + wn]);
        }
        int iRow = iBase + tid;
        g_posV[bj][iRow] = bpV;
        g_posI[bj][iRow] = bpI;
        g_negV[bj][iRow] = bnV;
        g_negI[bj][iRow] = bnI;

        if (!diag) {
            float qpV = -2.f, qnV = 3.5e38f;
            int qpI = 1 << 30, qnI = 1 << 30;
#pragma unroll
            for (int wm = 0; wm < 2; wm++) {
                selMax(qpV, qpI, sPosVc[tid * 2 + wm], sPosIc[tid * 2 + wm]);
                selMin(qnV, qnI, sNegVc[tid * 2 + wm], sNegIc[tid * 2 + wm]);
            }
            int jRow = jBase + tid;
            g_posV[bi][jRow] = qpV;
            g_posI[bi][jRow] = qpI;
            g_negV[bi][jRow] = qnV;
            g_negI[bi][jRow] = qnI;
        }
    }
}

// ===================== kernel 3: fused merge + exact loss + final reduce ==========
__global__ __launch_bounds__(256) void lossKernel(const float* __restrict__ emb,
                                                  float* __restrict__ out,
                                                  int D, int B) {
    int i = blockIdx.x;
    __shared__ int s_hp, s_hn, s_val;

    if (threadIdx.x < 32) {
        int c = threadIdx.x;    // NCHUNK == 32
        float pv = g_posV[c][i]; int pi = g_posI[c][i];
        float nv = g_negV[c][i]; int ni = g_negI[c][i];
#pragma unroll
        for (int off = 16; off > 0; off >>= 1) {
            float v2 = __shfl_xor_sync(0xFFFFFFFFu, pv, off);
            int   i2 = __shfl_xor_sync(0xFFFFFFFFu, pi, off);
            selMax(pv, pi, v2, i2);
            float v3 = __shfl_xor_sync(0xFFFFFFFFu, nv, off);
            int   i3 = __shfl_xor_sync(0xFFFFFFFFu, ni, off);
            selMin(nv, ni, v3, i3);
        }
        if (threadIdx.x == 0) {
            s_hp  = (pi < B) ? pi : 0;
            s_hn  = (ni < B) ? ni : 0;
            s_val = (pv > -0.5f) && (nv < 1e37f) ? 1 : 0;
        }
    }
    __syncthreads();

    int hp = s_hp, hn = s_hn;
    const float* a = emb + (size_t)i  * D;
    const float* p = emb + (size_t)hp * D;
    const float* n = emb + (size_t)hn * D;
    float sp = 0.f, sn = 0.f;
    for (int k = threadIdx.x * 4; k < D; k += blockDim.x * 4) {
        float4 va = *reinterpret_cast<const float4*>(a + k);
        float4 vp = *reinterpret_cast<const float4*>(p + k);
        float4 vn = *reinterpret_cast<const float4*>(n + k);
        float d;
        d = va.x - vp.x + 1e-6f; sp += d * d;
        d = va.y - vp.y + 1e-6f; sp += d * d;
        d = va.z - vp.z + 1e-6f; sp += d * d;
        d = va.w - vp.w + 1e-6f; sp += d * d;
        d = va.x - vn.x + 1e-6f; sn += d * d;
        d = va.y - vn.y + 1e-6f; sn += d * d;
        d = va.z - vn.z + 1e-6f; sn += d * d;
        d = va.w - vn.w + 1e-6f; sn += d * d;
    }
    for (int off = 16; off > 0; off >>= 1) {
        sp += __shfl_down_sync(0xFFFFFFFFu, sp, off);
        sn += __shfl_down_sync(0xFFFFFFFFu, sn, off);
    }
    __shared__ float wsp[8], wsn[8];
    int w = threadIdx.x >> 5;
    if ((threadIdx.x & 31) == 0) { wsp[w] = sp; wsn[w] = sn; }
    __syncthreads();

    __shared__ bool s_last;
    if (threadIdx.x == 0) {
        float tp = 0.f, tn = 0.f;
#pragma unroll
        for (int ww = 0; ww < 8; ww++) { tp += wsp[ww]; tn += wsn[ww]; }
        float per = fmaxf(sqrtf(tp) - sqrtf(tn) + 0.3f, 0.f);
        g_loss[i]  = s_val ? per : 0.f;
        g_valid[i] = s_val;
        __threadfence();
        int t = atomicAdd(&g_ticket, 1);
        s_last = (t == gridDim.x - 1);
    }
    __syncthreads();

    // last block performs the deterministic final reduction
    if (s_last) {
        float s = 0.f; int c = 0;
        for (int k = threadIdx.x; k < B; k += blockDim.x) {
            s += g_loss[k];
            c += g_valid[k];
        }
        for (int off = 16; off > 0; off >>= 1) {
            s += __shfl_down_sync(0xFFFFFFFFu, s, off);
            c += __shfl_down_sync(0xFFFFFFFFu, c, off);
        }
        __shared__ float fs[8];
        __shared__ int   fc[8];
        if ((threadIdx.x & 31) == 0) { fs[w] = s; fc[w] = c; }
        __syncthreads();
        if (threadIdx.x == 0) {
            float ts = 0.f; int tc = 0;
#pragma unroll
            for (int ww = 0; ww < 8; ww++) { ts += fs[ww]; tc += fc[ww]; }
            out[0] = (tc > 0) ? ts / (float)tc : 0.f;
        }
    }
}

// ===================== launch =====================
extern "C" void kernel_launch(void* const* d_in, const int* in_sizes, int n_in,
                              void* d_out, int out_size) {
    const float* emb    = (const float*)d_in[0];
    const int*   labels = (const int*)d_in[1];
    float*       out    = (float*)d_out;
    int B = in_sizes[1];
    int D = in_sizes[0] / B;

    cudaFuncSetAttribute(distKernel, cudaFuncAttributeMaxDynamicSharedMemorySize, SMEM_TOTAL);

    convKernel<<<B / 2, 256>>>(emb, D);
    int nb = B / BM;
    int ntiles = nb * (nb + 1) / 2;
    distKernel<<<ntiles, 256, SMEM_TOTAL>>>(labels, B, D);
    lossKernel<<<B, 256>>>(emb, out, D, B);
}

// round 7
// speedup vs baseline: 1.0319x; 1.0319x over previous
#include <cuda_runtime.h>
#include <cuda_bf16.h>
#include <cstdint>
#include <math.h>

// ===================== constants =====================
#define BMAX   4096
#define DMAX   2048
#define BM 128
#define BN 128
#define TBK 64                      // bf16 K per chunk = 128 bytes/row
#define STAGES 3
#define A_BYTES (BM*TBK*2)          // 16384
#define B_BYTES (BN*TBK*2)          // 16384
#define STAGE_BYTES (A_BYTES+B_BYTES)   // 32768
#define META_OFF (STAGES*STAGE_BYTES)   // 98304 (labels/sq, 2 KB)
#define SMEM_TOTAL (META_OFF + 2048)    // 100352 -> 2 CTAs/SM
#define NCHUNK (BMAX/BN)            // 32

// ===================== device scratch =====================
__device__ __nv_bfloat16 g_ebf[(size_t)BMAX * DMAX];
__device__ float g_sq[BMAX];
__device__ float g_posV[NCHUNK][BMAX];
__device__ int   g_posI[NCHUNK][BMAX];
__device__ float g_negV[NCHUNK][BMAX];
__device__ int   g_negI[NCHUNK][BMAX];
__device__ int   g_valid[BMAX];
__device__ float g_loss[BMAX];

// ===================== helpers =====================
__device__ __forceinline__ uint32_t smem_u32(const void* p) {
    uint32_t a;
    asm("{ .reg .u64 t; cvta.to.shared.u64 t, %1; cvt.u32.u64 %0, t; }" : "=r"(a) : "l"(p));
    return a;
}
__device__ __forceinline__ void cpa16(uint32_t s, const void* g) {
    asm volatile("cp.async.cg.shared.global [%0], [%1], 16;" :: "r"(s), "l"(g));
}
#define CPA_COMMIT() asm volatile("cp.async.commit_group;" ::: "memory")
#define CPA_WAIT(N)  asm volatile("cp.async.wait_group %0;" :: "n"(N) : "memory")

__device__ __forceinline__ void ldsm4(uint32_t* r, uint32_t addr) {
    asm volatile("ldmatrix.sync.aligned.m8n8.x4.shared.b16 {%0,%1,%2,%3}, [%4];"
                 : "=r"(r[0]), "=r"(r[1]), "=r"(r[2]), "=r"(r[3]) : "r"(addr));
}
__device__ __forceinline__ void mma16816(float* c, const uint32_t* a, const uint32_t* b) {
    asm volatile(
        "mma.sync.aligned.m16n8k16.row.col.f32.bf16.bf16.f32 "
        "{%0,%1,%2,%3}, {%4,%5,%6,%7}, {%8,%9}, {%0,%1,%2,%3};"
        : "+f"(c[0]), "+f"(c[1]), "+f"(c[2]), "+f"(c[3])
        : "r"(a[0]), "r"(a[1]), "r"(a[2]), "r"(a[3]), "r"(b[0]), "r"(b[1]));
}

__device__ __forceinline__ void selMax(float& v, int& i, float nv, int ni) {
    if (nv > v || (nv == v && ni < i)) { v = nv; i = ni; }
}
__device__ __forceinline__ void selMin(float& v, int& i, float nv, int ni) {
    if (nv < v || (nv == v && ni < i)) { v = nv; i = ni; }
}

// ===================== kernel 1: fp32 -> bf16 + row sumsq (warp-per-row) ==========
__global__ __launch_bounds__(256) void convKernel(const float* __restrict__ emb, int D) {
    const int warp = threadIdx.x >> 5;
    const int lane = threadIdx.x & 31;
    const int i = blockIdx.x * 8 + warp;
    const float4* row = reinterpret_cast<const float4*>(emb + (size_t)i * D);
    __nv_bfloat162* orow = reinterpret_cast<__nv_bfloat162*>(g_ebf + (size_t)i * D);

    float s = 0.f;
    // D = 2048 -> 512 float4 per row -> 16 per lane, all independent (high MLP)
#pragma unroll
    for (int t = 0; t < 16; t++) {
        int k = lane + 32 * t;
        float4 v = row[k];
        s += v.x * v.x + v.y * v.y + v.z * v.z + v.w * v.w;
        __nv_bfloat162 h0, h1;
        h0.x = __float2bfloat16(v.x); h0.y = __float2bfloat16(v.y);
        h1.x = __float2bfloat16(v.z); h1.y = __float2bfloat16(v.w);
        orow[2 * k] = h0; orow[2 * k + 1] = h1;
    }
#pragma unroll
    for (int off = 16; off > 0; off >>= 1)
        s += __shfl_down_sync(0xFFFFFFFFu, s, off);
    if (lane == 0) g_sq[i] = s;
}

// ===================== kernel 2: bf16 HMMA GEMM (upper triangle) + dual selection ==========
__device__ __forceinline__ void load_chunk(int tid, uint32_t sbase, int s,
                                           int iBase, int jBase, int c, int D) {
    uint32_t sA = sbase + s * STAGE_BYTES;
    uint32_t sB = sA + A_BYTES;
    int k0 = c * TBK;
    const char* gA = (const char*)(g_ebf + (size_t)iBase * D + k0);
    const char* gB = (const char*)(g_ebf + (size_t)jBase * D + k0);
#pragma unroll
    for (int t = 0; t < 4; t++) {
        int f = tid + t * 256;
        int row = f >> 3, c16 = f & 7;
        int colb = c16 * 16;
        uint32_t off = (uint32_t)(row * 128 + (colb ^ ((row & 7) << 4)));
        cpa16(sA + off, gA + (size_t)row * (size_t)(D * 2) + colb);
    }
#pragma unroll
    for (int t = 0; t < 4; t++) {
        int f = tid + t * 256;
        int row = f >> 3, c16 = f & 7;
        int colb = c16 * 16;
        uint32_t off = (uint32_t)(row * 128 + (colb ^ ((row & 7) << 4)));
        cpa16(sB + off, gB + (size_t)row * (size_t)(D * 2) + colb);
    }
    CPA_COMMIT();
}

__global__ __launch_bounds__(256, 2) void distKernel(const int* __restrict__ labels,
                                                     int B, int D) {
    extern __shared__ char sm[];
    uint32_t sbase = smem_u32(sm);

    const int tid  = threadIdx.x;
    const int wid  = tid >> 5;
    const int lane = tid & 31;
    const int warpM = wid & 1;       // 0..1 (64 rows each)
    const int warpN = wid >> 1;      // 0..3 (32 cols each)

    // decode upper-triangular tile (bi <= bj)
    const int nb = B / BM;           // 32
    int bi = 0, rem = blockIdx.x;
    while (rem >= nb - bi) { rem -= nb - bi; bi++; }
    const int bj = bi + rem;
    const int iBase = bi * BM;
    const int jBase = bj * BN;
    const bool diag = (bi == bj);

    int*   sLabJ = (int*)  (sm + META_OFF);
    float* sSqJ  = (float*)(sm + META_OFF + 512);
    int*   sLabI = (int*)  (sm + META_OFF + 1024);
    float* sSqI  = (float*)(sm + META_OFF + 1536);
    float* sPosV  = (float*)(sm);
    int*   sPosI  = (int*)  (sm + 2048);
    float* sNegV  = (float*)(sm + 4096);
    int*   sNegI  = (int*)  (sm + 6144);
    float* sPosVc = (float*)(sm + 8192);
    int*   sPosIc = (int*)  (sm + 9216);
    float* sNegVc = (float*)(sm + 10240);
    int*   sNegIc = (int*)  (sm + 11264);

    if (tid < 128) {
        sLabJ[tid] = labels[jBase + tid];
        sSqJ[tid]  = g_sq[jBase + tid];
        sLabI[tid] = labels[iBase + tid];
        sSqI[tid]  = g_sq[iBase + tid];
    }

    const int rowA_l = (lane & 7) + ((lane >> 3) & 1) * 8;
    const int colA_b = (lane >> 4) * 16;
    const int rowB_l = (lane & 7) + (lane >> 4) * 8;
    const int colB_b = ((lane >> 3) & 1) * 16;

    int aRow[4], bRow[2];
#pragma unroll
    for (int mf = 0; mf < 4; mf++) aRow[mf] = warpM * 64 + mf * 16 + rowA_l;
#pragma unroll
    for (int nf = 0; nf < 2; nf++) bRow[nf] = warpN * 32 + nf * 16 + rowB_l;

    float acc[4][4][4];
#pragma unroll
    for (int a = 0; a < 4; a++)
#pragma unroll
        for (int b = 0; b < 4; b++)
#pragma unroll
            for (int c = 0; c < 4; c++) acc[a][b][c] = 0.f;

    const int nch = D / TBK;     // 32

    load_chunk(tid, sbase, 0, iBase, jBase, 0, D);
    load_chunk(tid, sbase, 1, iBase, jBase, 1, D);

    for (int c = 0; c < nch; c++) {
        if (c == nch - 1) { CPA_WAIT(0); } else { CPA_WAIT(1); }
        __syncthreads();
        if (c + 2 < nch)
            load_chunk(tid, sbase, (c + 2) % STAGES, iBase, jBase, c + 2, D);

        uint32_t sA = sbase + (c % STAGES) * STAGE_BYTES;
        uint32_t sB = sA + A_BYTES;
#pragma unroll
        for (int ks = 0; ks < TBK / 16; ks++) {
            uint32_t aF[16], bF[8];
#pragma unroll
            for (int mf = 0; mf < 4; mf++) {
                int r = aRow[mf];
                uint32_t addr = sA + r * 128 + ((ks * 32 + colA_b) ^ ((r & 7) << 4));
                ldsm4(aF + mf * 4, addr);
            }
#pragma unroll
            for (int nf = 0; nf < 2; nf++) {
                int r = bRow[nf];
                uint32_t addr = sB + r * 128 + ((ks * 32 + colB_b) ^ ((r & 7) << 4));
                ldsm4(bF + nf * 4, addr);
            }
#pragma unroll
            for (int mf = 0; mf < 4; mf++)
#pragma unroll
                for (int n8 = 0; n8 < 4; n8++)
                    mma16816(acc[mf][n8], aF + mf * 4, bF + n8 * 2);
        }
    }
    __syncthreads();

    // ---- epilogue: d^2 + dual hard pos/neg selection ----
    const int g = lane >> 2;
    const int q = lane & 3;

    int   jLab[8];
    float jSq[8];
    int   jIdx[8];
#pragma unroll
    for (int n8 = 0; n8 < 4; n8++)
#pragma unroll
        for (int cc = 0; cc < 2; cc++) {
            int jj = warpN * 32 + n8 * 8 + q * 2 + cc;
            jLab[n8 * 2 + cc] = sLabJ[jj];
            jSq[n8 * 2 + cc]  = sSqJ[jj];
            jIdx[n8 * 2 + cc] = jBase + jj;
        }

    float cpV[8], cnV[8];
    int   cpI[8], cnI[8];
#pragma unroll
    for (int t = 0; t < 8; t++) {
        cpV[t] = -1.f; cpI[t] = 1 << 30;
        cnV[t] = 3.4e38f; cnI[t] = 1 << 30;
    }

#pragma unroll
    for (int mf = 0; mf < 4; mf++) {
#pragma unroll
        for (int h = 0; h < 2; h++) {
            int rl   = warpM * 64 + mf * 16 + h * 8 + g;
            int iRow = iBase + rl;
            float sqi = sSqI[rl];
            int   lab = sLabI[rl];
            float bpV = -1.f, bnV = 3.4e38f;
            int   bpI = 1 << 30, bnI = 1 << 30;
#pragma unroll
            for (int t = 0; t < 8; t++) {
                int n8 = t >> 1, cc = t & 1;
                int j = jIdx[t];
                float dot = acc[mf][n8][h * 2 + cc];
                float d2 = fmaxf(sqi + jSq[t] - 2.f * dot, 0.f);
                if (jLab[t] == lab) {
                    if (j != iRow) {
                        selMax(bpV, bpI, d2, j);
                        selMax(cpV[t], cpI[t], d2, iRow);
                    }
                } else {
                    selMin(bnV, bnI, d2, j);
                    selMin(cnV[t], cnI[t], d2, iRow);
                }
            }
#pragma unroll
            for (int off = 1; off <= 2; off <<= 1) {
                float pv = __shfl_xor_sync(0xFFFFFFFFu, bpV, off);
                int   pi = __shfl_xor_sync(0xFFFFFFFFu, bpI, off);
                selMax(bpV, bpI, pv, pi);
                float nv = __shfl_xor_sync(0xFFFFFFFFu, bnV, off);
                int   ni = __shfl_xor_sync(0xFFFFFFFFu, bnI, off);
                selMin(bnV, bnI, nv, ni);
            }
            if (q == 0) {
                sPosV[rl * 4 + warpN] = bpV;
                sPosI[rl * 4 + warpN] = bpI;
                sNegV[rl * 4 + warpN] = bnV;
                sNegI[rl * 4 + warpN] = bnI;
            }
        }
    }

    if (!diag) {
#pragma unroll
        for (int t = 0; t < 8; t++) {
#pragma unroll
            for (int off = 4; off <= 16; off <<= 1) {
                float pv = __shfl_xor_sync(0xFFFFFFFFu, cpV[t], off);
                int   pi = __shfl_xor_sync(0xFFFFFFFFu, cpI[t], off);
                selMax(cpV[t], cpI[t], pv, pi);
                float nv = __shfl_xor_sync(0xFFFFFFFFu, cnV[t], off);
                int   ni = __shfl_xor_sync(0xFFFFFFFFu, cnI[t], off);
                selMin(cnV[t], cnI[t], nv, ni);
            }
        }
        if (g == 0) {
#pragma unroll
            for (int t = 0; t < 8; t++) {
                int n8 = t >> 1, cc = t & 1;
                int jj = warpN * 32 + n8 * 8 + q * 2 + cc;
                sPosVc[jj * 2 + warpM] = cpV[t];
                sPosIc[jj * 2 + warpM] = cpI[t];
                sNegVc[jj * 2 + warpM] = cnV[t];
                sNegIc[jj * 2 + warpM] = cnI[t];
            }
        }
    }
    __syncthreads();

    if (tid < 128) {
        float bpV = -2.f, bnV = 3.5e38f;
        int bpI = 1 << 30, bnI = 1 << 30;
#pragma unroll
        for (int wn = 0; wn < 4; wn++) {
            selMax(bpV, bpI, sPosV[tid * 4 + wn], sPosI[tid * 4 + wn]);
            selMin(bnV, bnI, sNegV[tid * 4 + wn], sNegI[tid * 4 + wn]);
        }
        int iRow = iBase + tid;
        g_posV[bj][iRow] = bpV;
        g_posI[bj][iRow] = bpI;
        g_negV[bj][iRow] = bnV;
        g_negI[bj][iRow] = bnI;

        if (!diag) {
            float qpV = -2.f, qnV = 3.5e38f;
            int qpI = 1 << 30, qnI = 1 << 30;
#pragma unroll
            for (int wm = 0; wm < 2; wm++) {
                selMax(qpV, qpI, sPosVc[tid * 2 + wm], sPosIc[tid * 2 + wm]);
                selMin(qnV, qnI, sNegVc[tid * 2 + wm], sNegIc[tid * 2 + wm]);
            }
            int jRow = jBase + tid;
            g_posV[bi][jRow] = qpV;
            g_posI[bi][jRow] = qpI;
            g_negV[bi][jRow] = qnV;
            g_negI[bi][jRow] = qnI;
        }
    }
}

// ===================== kernel 3: fused merge + exact dp/dn loss =====================
__global__ __launch_bounds__(256) void lossKernel(const float* __restrict__ emb,
                                                  int D, int B) {
    int i = blockIdx.x;
    __shared__ int s_hp, s_hn, s_val;

    if (threadIdx.x < 32) {
        int c = threadIdx.x;    // NCHUNK == 32
        float pv = g_posV[c][i]; int pi = g_posI[c][i];
        float nv = g_negV[c][i]; int ni = g_negI[c][i];
#pragma unroll
        for (int off = 16; off > 0; off >>= 1) {
            float v2 = __shfl_xor_sync(0xFFFFFFFFu, pv, off);
            int   i2 = __shfl_xor_sync(0xFFFFFFFFu, pi, off);
            selMax(pv, pi, v2, i2);
            float v3 = __shfl_xor_sync(0xFFFFFFFFu, nv, off);
            int   i3 = __shfl_xor_sync(0xFFFFFFFFu, ni, off);
            selMin(nv, ni, v3, i3);
        }
        if (threadIdx.x == 0) {
            s_hp  = (pi < B) ? pi : 0;
            s_hn  = (ni < B) ? ni : 0;
            s_val = (pv > -0.5f) && (nv < 1e37f) ? 1 : 0;
        }
    }
    __syncthreads();

    int hp = s_hp, hn = s_hn;
    const float* a = emb + (size_t)i  * D;
    const float* p = emb + (size_t)hp * D;
    const float* n = emb + (size_t)hn * D;
    float sp = 0.f, sn = 0.f;
    for (int k = threadIdx.x * 4; k < D; k += blockDim.x * 4) {
        float4 va = *reinterpret_cast<const float4*>(a + k);
        float4 vp = *reinterpret_cast<const float4*>(p + k);
        float4 vn = *reinterpret_cast<const float4*>(n + k);
        float d;
        d = va.x - vp.x + 1e-6f; sp += d * d;
        d = va.y - vp.y + 1e-6f; sp += d * d;
        d = va.z - vp.z + 1e-6f; sp += d * d;
        d = va.w - vp.w + 1e-6f; sp += d * d;
        d = va.x - vn.x + 1e-6f; sn += d * d;
        d = va.y - vn.y + 1e-6f; sn += d * d;
        d = va.z - vn.z + 1e-6f; sn += d * d;
        d = va.w - vn.w + 1e-6f; sn += d * d;
    }
    for (int off = 16; off > 0; off >>= 1) {
        sp += __shfl_down_sync(0xFFFFFFFFu, sp, off);
        sn += __shfl_down_sync(0xFFFFFFFFu, sn, off);
    }
    __shared__ float wsp[8], wsn[8];
    int w = threadIdx.x >> 5;
    if ((threadIdx.x & 31) == 0) { wsp[w] = sp; wsn[w] = sn; }
    __syncthreads();
    if (threadIdx.x == 0) {
        float tp = 0.f, tn = 0.f;
#pragma unroll
        for (int ww = 0; ww < 8; ww++) { tp += wsp[ww]; tn += wsn[ww]; }
        float per = fmaxf(sqrtf(tp) - sqrtf(tn) + 0.3f, 0.f);
        g_loss[i]  = s_val ? per : 0.f;
        g_valid[i] = s_val;
    }
}

// ===================== kernel 4: final reduction =====================
__global__ void finalKernel(float* __restrict__ out, int B) {
    __shared__ float ssum[1024];
    __shared__ int   scnt[1024];
    float s = 0.f; int c = 0;
    for (int i = threadIdx.x; i < B; i += 1024) {
        s += g_loss[i];
        c += g_valid[i];
    }
    ssum[threadIdx.x] = s;
    scnt[threadIdx.x] = c;
    __syncthreads();
    for (int off = 512; off > 0; off >>= 1) {
        if (threadIdx.x < off) {
            ssum[threadIdx.x] += ssum[threadIdx.x + off];
            scnt[threadIdx.x] += scnt[threadIdx.x + off];
        }
        __syncthreads();
    }
    if (threadIdx.x == 0)
        out[0] = (scnt[0] > 0) ? ssum[0] / (float)scnt[0] : 0.f;
}

// ===================== launch =====================
extern "C" void kernel_launch(void* const* d_in, const int* in_sizes, int n_in,
                              void* d_out, int out_size) {
    const float* emb    = (const float*)d_in[0];
    const int*   labels = (const int*)d_in[1];
    float*       out    = (float*)d_out;
    int B = in_sizes[1];
    int D = in_sizes[0] / B;

    cudaFuncSetAttribute(distKernel, cudaFuncAttributeMaxDynamicSharedMemorySize, SMEM_TOTAL);

    convKernel<<<B / 8, 256>>>(emb, D);
    int nb = B / BM;
    int ntiles = nb * (nb + 1) / 2;
    distKernel<<<ntiles, 256, SMEM_TOTAL>>>(labels, B, D);
    lossKernel<<<B, 256>>>(emb, D, B);
    finalKernel<<<1, 1024>>>(out, B);
}

// round 9
// speedup vs baseline: 1.0442x; 1.0119x over previous
#include <cuda_runtime.h>
#include <cuda_bf16.h>
#include <cstdint>
#include <math.h>

// ===================== constants =====================
#define BMAX   4096
#define DMAX   2048
#define BM 128
#define BN 128
#define TBK 64                      // bf16 K per chunk = 128 bytes/row
#define STAGES 3
#define A_BYTES (BM*TBK*2)          // 16384
#define B_BYTES (BN*TBK*2)          // 16384
#define STAGE_BYTES (A_BYTES+B_BYTES)   // 32768
#define META_OFF (STAGES*STAGE_BYTES)   // 98304 (labels/sq, 2 KB)
#define SMEM_TOTAL (META_OFF + 2048)    // 100352 -> 2 CTAs/SM
#define NCHUNK (BMAX/BN)            // 32

// ===================== device scratch =====================
__device__ __nv_bfloat16 g_ebf[(size_t)BMAX * DMAX];
__device__ float g_sq[BMAX];
__device__ float g_posV[NCHUNK][BMAX];
__device__ int   g_posI[NCHUNK][BMAX];
__device__ float g_negV[NCHUNK][BMAX];
__device__ int   g_negI[NCHUNK][BMAX];
__device__ int   g_valid[BMAX];
__device__ float g_loss[BMAX];

// ===================== helpers =====================
__device__ __forceinline__ uint32_t smem_u32(const void* p) {
    uint32_t a;
    asm("{ .reg .u64 t; cvta.to.shared.u64 t, %1; cvt.u32.u64 %0, t; }" : "=r"(a) : "l"(p));
    return a;
}
__device__ __forceinline__ void cpa16(uint32_t s, const void* g) {
    asm volatile("cp.async.cg.shared.global [%0], [%1], 16;" :: "r"(s), "l"(g));
}
#define CPA_COMMIT() asm volatile("cp.async.commit_group;" ::: "memory")
#define CPA_WAIT(N)  asm volatile("cp.async.wait_group %0;" :: "n"(N) : "memory")

__device__ __forceinline__ void ldsm4(uint32_t* r, uint32_t addr) {
    asm volatile("ldmatrix.sync.aligned.m8n8.x4.shared.b16 {%0,%1,%2,%3}, [%4];"
                 : "=r"(r[0]), "=r"(r[1]), "=r"(r[2]), "=r"(r[3]) : "r"(addr));
}
__device__ __forceinline__ void mma16816(float* c, const uint32_t* a, const uint32_t* b) {
    asm volatile(
        "mma.sync.aligned.m16n8k16.row.col.f32.bf16.bf16.f32 "
        "{%0,%1,%2,%3}, {%4,%5,%6,%7}, {%8,%9}, {%0,%1,%2,%3};"
        : "+f"(c[0]), "+f"(c[1]), "+f"(c[2]), "+f"(c[3])
        : "r"(a[0]), "r"(a[1]), "r"(a[2]), "r"(a[3]), "r"(b[0]), "r"(b[1]));
}

__device__ __forceinline__ void selMax(float& v, int& i, float nv, int ni) {
    if (nv > v || (nv == v && ni < i)) { v = nv; i = ni; }
}
__device__ __forceinline__ void selMin(float& v, int& i, float nv, int ni) {
    if (nv < v || (nv == v && ni < i)) { v = nv; i = ni; }
}

// ===================== kernel 1: fp32 -> bf16 + row sumsq (warp-per-row) ==========
__global__ __launch_bounds__(256) void convKernel(const float* __restrict__ emb, int D) {
    const int warp = threadIdx.x >> 5;
    const int lane = threadIdx.x & 31;
    const int i = blockIdx.x * 8 + warp;
    const float4* row = reinterpret_cast<const float4*>(emb + (size_t)i * D);
    __nv_bfloat162* orow = reinterpret_cast<__nv_bfloat162*>(g_ebf + (size_t)i * D);

    float s = 0.f;
#pragma unroll
    for (int t = 0; t < 16; t++) {
        int k = lane + 32 * t;
        float4 v = row[k];
        s += v.x * v.x + v.y * v.y + v.z * v.z + v.w * v.w;
        __nv_bfloat162 h0, h1;
        h0.x = __float2bfloat16(v.x); h0.y = __float2bfloat16(v.y);
        h1.x = __float2bfloat16(v.z); h1.y = __float2bfloat16(v.w);
        orow[2 * k] = h0; orow[2 * k + 1] = h1;
    }
#pragma unroll
    for (int off = 16; off > 0; off >>= 1)
        s += __shfl_down_sync(0xFFFFFFFFu, s, off);
    if (lane == 0) g_sq[i] = s;
}

// ===================== kernel 2: bf16 HMMA GEMM (upper triangle) + dual selection ==========
__device__ __forceinline__ void load_chunk(int tid, uint32_t sbase, int s,
                                           int iBase, int jBase, int c, int D) {
    uint32_t sA = sbase + s * STAGE_BYTES;
    uint32_t sB = sA + A_BYTES;
    int k0 = c * TBK;
    const char* gA = (const char*)(g_ebf + (size_t)iBase * D + k0);
    const char* gB = (const char*)(g_ebf + (size_t)jBase * D + k0);
#pragma unroll
    for (int t = 0; t < 4; t++) {
        int f = tid + t * 256;
        int row = f >> 3, c16 = f & 7;
        int colb = c16 * 16;
        uint32_t off = (uint32_t)(row * 128 + (colb ^ ((row & 7) << 4)));
        cpa16(sA + off, gA + (size_t)row * (size_t)(D * 2) + colb);
    }
#pragma unroll
    for (int t = 0; t < 4; t++) {
        int f = tid + t * 256;
        int row = f >> 3, c16 = f & 7;
        int colb = c16 * 16;
        uint32_t off = (uint32_t)(row * 128 + (colb ^ ((row & 7) << 4)));
        cpa16(sB + off, gB + (size_t)row * (size_t)(D * 2) + colb);
    }
    CPA_COMMIT();
}

__global__ __launch_bounds__(256, 2) void distKernel(const int* __restrict__ labels,
                                                     int B, int D) {
    extern __shared__ char sm[];
    uint32_t sbase = smem_u32(sm);

    const int tid  = threadIdx.x;
    const int wid  = tid >> 5;
    const int lane = tid & 31;
    const int warpM = wid & 1;       // 0..1 (64 rows each)
    const int warpN = wid >> 1;      // 0..3 (32 cols each)

    // decode upper-triangular tile (bi <= bj)
    const int nb = B / BM;           // 32
    int bi = 0, rem = blockIdx.x;
    while (rem >= nb - bi) { rem -= nb - bi; bi++; }
    const int bj = bi + rem;
    const int iBase = bi * BM;
    const int jBase = bj * BN;
    const bool diag = (bi == bj);

    int*   sLabJ = (int*)  (sm + META_OFF);
    float* sSqJ  = (float*)(sm + META_OFF + 512);
    int*   sLabI = (int*)  (sm + META_OFF + 1024);
    float* sSqI  = (float*)(sm + META_OFF + 1536);
    float* sPosV  = (float*)(sm);
    int*   sPosI  = (int*)  (sm + 2048);
    float* sNegV  = (float*)(sm + 4096);
    int*   sNegI  = (int*)  (sm + 6144);
    float* sPosVc = (float*)(sm + 8192);
    int*   sPosIc = (int*)  (sm + 9216);
    float* sNegVc = (float*)(sm + 10240);
    int*   sNegIc = (int*)  (sm + 11264);

    if (tid < 128) {
        sLabJ[tid] = labels[jBase + tid];
        sSqJ[tid]  = g_sq[jBase + tid];
        sLabI[tid] = labels[iBase + tid];
        sSqI[tid]  = g_sq[iBase + tid];
    }

    const int rowA_l = (lane & 7) + ((lane >> 3) & 1) * 8;
    const int colA_b = (lane >> 4) * 16;
    const int rowB_l = (lane & 7) + (lane >> 4) * 8;
    const int colB_b = ((lane >> 3) & 1) * 16;

    int aRow[4], bRow[2];
#pragma unroll
    for (int mf = 0; mf < 4; mf++) aRow[mf] = warpM * 64 + mf * 16 + rowA_l;
#pragma unroll
    for (int nf = 0; nf < 2; nf++) bRow[nf] = warpN * 32 + nf * 16 + rowB_l;

    float acc[4][4][4];
#pragma unroll
    for (int a = 0; a < 4; a++)
#pragma unroll
        for (int b = 0; b < 4; b++)
#pragma unroll
            for (int c = 0; c < 4; c++) acc[a][b][c] = 0.f;

    const int nch = D / TBK;     // 32

    load_chunk(tid, sbase, 0, iBase, jBase, 0, D);
    load_chunk(tid, sbase, 1, iBase, jBase, 1, D);

    for (int c = 0; c < nch; c++) {
        if (c == nch - 1) { CPA_WAIT(0); } else { CPA_WAIT(1); }
        __syncthreads();
        if (c + 2 < nch)
            load_chunk(tid, sbase, (c + 2) % STAGES, iBase, jBase, c + 2, D);

        uint32_t sA = sbase + (c % STAGES) * STAGE_BYTES;
        uint32_t sB = sA + A_BYTES;

        // software-pipelined fragment loads: double-buffered ldsm ahead of MMA
        uint32_t aF[2][16], bF[2][8];
#pragma unroll
        for (int mf = 0; mf < 4; mf++) {
            int r = aRow[mf];
            ldsm4(aF[0] + mf * 4, sA + r * 128 + ((colA_b) ^ ((r & 7) << 4)));
        }
#pragma unroll
        for (int nf = 0; nf < 2; nf++) {
            int r = bRow[nf];
            ldsm4(bF[0] + nf * 4, sB + r * 128 + ((colB_b) ^ ((r & 7) << 4)));
        }
#pragma unroll
        for (int ks = 0; ks < TBK / 16; ks++) {
            const int cur = ks & 1, nxt = cur ^ 1;
            if (ks < TBK / 16 - 1) {
#pragma unroll
                for (int mf = 0; mf < 4; mf++) {
                    int r = aRow[mf];
                    ldsm4(aF[nxt] + mf * 4,
                          sA + r * 128 + (((ks + 1) * 32 + colA_b) ^ ((r & 7) << 4)));
                }
#pragma unroll
                for (int nf = 0; nf < 2; nf++) {
                    int r = bRow[nf];
                    ldsm4(bF[nxt] + nf * 4,
                          sB + r * 128 + (((ks + 1) * 32 + colB_b) ^ ((r & 7) << 4)));
                }
            }
#pragma unroll
            for (int mf = 0; mf < 4; mf++)
#pragma unroll
                for (int n8 = 0; n8 < 4; n8++)
                    mma16816(acc[mf][n8], aF[cur] + mf * 4, bF[cur] + n8 * 2);
        }
    }
    __syncthreads();

    // ---- epilogue: d^2 + dual hard pos/neg selection ----
    const int g = lane >> 2;
    const int q = lane & 3;

    int   jLab[8];
    float jSq[8];
    int   jIdx[8];
#pragma unroll
    for (int n8 = 0; n8 < 4; n8++)
#pragma unroll
        for (int cc = 0; cc < 2; cc++) {
            int jj = warpN * 32 + n8 * 8 + q * 2 + cc;
            jLab[n8 * 2 + cc] = sLabJ[jj];
            jSq[n8 * 2 + cc]  = sSqJ[jj];
            jIdx[n8 * 2 + cc] = jBase + jj;
        }

    float cpV[8], cnV[8];
    int   cpI[8], cnI[8];
#pragma unroll
    for (int t = 0; t < 8; t++) {
        cpV[t] = -1.f; cpI[t] = 1 << 30;
        cnV[t] = 3.4e38f; cnI[t] = 1 << 30;
    }

#pragma unroll
    for (int mf = 0; mf < 4; mf++) {
#pragma unroll
        for (int h = 0; h < 2; h++) {
            int rl   = warpM * 64 + mf * 16 + h * 8 + g;
            int iRow = iBase + rl;
            float sqi = sSqI[rl];
            int   lab = sLabI[rl];
            float bpV = -1.f, bnV = 3.4e38f;
            int   bpI = 1 << 30, bnI = 1 << 30;
#pragma unroll
            for (int t = 0; t < 8; t++) {
                int n8 = t >> 1, cc = t & 1;
                int j = jIdx[t];
                float dot = acc[mf][n8][h * 2 + cc];
                float d2 = fmaxf(sqi + jSq[t] - 2.f * dot, 0.f);
                if (jLab[t] == lab) {
                    if (j != iRow) {
                        selMax(bpV, bpI, d2, j);
                        selMax(cpV[t], cpI[t], d2, iRow);
                    }
                } else {
                    selMin(bnV, bnI, d2, j);
                    selMin(cnV[t], cnI[t], d2, iRow);
                }
            }
#pragma unroll
            for (int off = 1; off <= 2; off <<= 1) {
                float pv = __shfl_xor_sync(0xFFFFFFFFu, bpV, off);
                int   pi = __shfl_xor_sync(0xFFFFFFFFu, bpI, off);
                selMax(bpV, bpI, pv, pi);
                float nv = __shfl_xor_sync(0xFFFFFFFFu, bnV, off);
                int   ni = __shfl_xor_sync(0xFFFFFFFFu, bnI, off);
                selMin(bnV, bnI, nv, ni);
            }
            if (q == 0) {
                sPosV[rl * 4 + warpN] = bpV;
                sPosI[rl * 4 + warpN] = bpI;
                sNegV[rl * 4 + warpN] = bnV;
                sNegI[rl * 4 + warpN] = bnI;
            }
        }
    }

    if (!diag) {
#pragma unroll
        for (int t = 0; t < 8; t++) {
#pragma unroll
            for (int off = 4; off <= 16; off <<= 1) {
                float pv = __shfl_xor_sync(0xFFFFFFFFu, cpV[t], off);
                int   pi = __shfl_xor_sync(0xFFFFFFFFu, cpI[t], off);
                selMax(cpV[t], cpI[t], pv, pi);
                float nv = __shfl_xor_sync(0xFFFFFFFFu, cnV[t], off);
                int   ni = __shfl_xor_sync(0xFFFFFFFFu, cnI[t], off);
                selMin(cnV[t], cnI[t], nv, ni);
            }
        }
        if (g == 0) {
#pragma unroll
            for (int t = 0; t < 8; t++) {
                int n8 = t >> 1, cc = t & 1;
                int jj = warpN * 32 + n8 * 8 + q * 2 + cc;
                sPosVc[jj * 2 + warpM] = cpV[t];
                sPosIc[jj * 2 + warpM] = cpI[t];
                sNegVc[jj * 2 + warpM] = cnV[t];
                sNegIc[jj * 2 + warpM] = cnI[t];
            }
        }
    }
    __syncthreads();

    if (tid < 128) {
        float bpV = -2.f, bnV = 3.5e38f;
        int bpI = 1 << 30, bnI = 1 << 30;
#pragma unroll
        for (int wn = 0; wn < 4; wn++) {
            selMax(bpV, bpI, sPosV[tid * 4 + wn], sPosI[tid * 4 + wn]);
            selMin(bnV, bnI, sNegV[tid * 4 + wn], sNegI[tid * 4 + wn]);
        }
        int iRow = iBase + tid;
        g_posV[bj][iRow] = bpV;
        g_posI[bj][iRow] = bpI;
        g_negV[bj][iRow] = bnV;
        g_negI[bj][iRow] = bnI;

        if (!diag) {
            float qpV = -2.f, qnV = 3.5e38f;
            int qpI = 1 << 30, qnI = 1 << 30;
#pragma unroll
            for (int wm = 0; wm < 2; wm++) {
                selMax(qpV, qpI, sPosVc[tid * 2 + wm], sPosIc[tid * 2 + wm]);
                selMin(qnV, qnI, sNegVc[tid * 2 + wm], sNegIc[tid * 2 + wm]);
            }
            int jRow = jBase + tid;
            g_posV[bi][jRow] = qpV;
            g_posI[bi][jRow] = qpI;
            g_negV[bi][jRow] = qnV;
            g_negI[bi][jRow] = qnI;
        }
    }
}

// ===================== kernel 3: fused merge + exact dp/dn loss =====================
__global__ __launch_bounds__(256) void lossKernel(const float* __restrict__ emb,
                                                  int D, int B) {
    int i = blockIdx.x;
    __shared__ int s_hp, s_hn, s_val;

    if (threadIdx.x < 32) {
        int c = threadIdx.x;    // NCHUNK == 32
        float pv = g_posV[c][i]; int pi = g_posI[c][i];
        float nv = g_negV[c][i]; int ni = g_negI[c][i];
#pragma unroll
        for (int off = 16; off > 0; off >>= 1) {
            float v2 = __shfl_xor_sync(0xFFFFFFFFu, pv, off);
            int   i2 = __shfl_xor_sync(0xFFFFFFFFu, pi, off);
            selMax(pv, pi, v2, i2);
            float v3 = __shfl_xor_sync(0xFFFFFFFFu, nv, off);
            int   i3 = __shfl_xor_sync(0xFFFFFFFFu, ni, off);
            selMin(nv, ni, v3, i3);
        }
        if (threadIdx.x == 0) {
            s_hp  = (pi < B) ? pi : 0;
            s_hn  = (ni < B) ? ni : 0;
            s_val = (pv > -0.5f) && (nv < 1e37f) ? 1 : 0;
        }
    }
    __syncthreads();

    int hp = s_hp, hn = s_hn;
    const float* a = emb + (size_t)i  * D;
    const float* p = emb + (size_t)hp * D;
    const float* n = emb + (size_t)hn * D;
    float sp = 0.f, sn = 0.f;
    for (int k = threadIdx.x * 4; k < D; k += blockDim.x * 4) {
        float4 va = *reinterpret_cast<const float4*>(a + k);
        float4 vp = *reinterpret_cast<const float4*>(p + k);
        float4 vn = *reinterpret_cast<const float4*>(n + k);
        float d;
        d = va.x - vp.x + 1e-6f; sp += d * d;
        d = va.y - vp.y + 1e-6f; sp += d * d;
        d = va.z - vp.z + 1e-6f; sp += d * d;
        d = va.w - vp.w + 1e-6f; sp += d * d;
        d = va.x - vn.x + 1e-6f; sn += d * d;
        d = va.y - vn.y + 1e-6f; sn += d * d;
        d = va.z - vn.z + 1e-6f; sn += d * d;
        d = va.w - vn.w + 1e-6f; sn += d * d;
    }
    for (int off = 16; off > 0; off >>= 1) {
        sp += __shfl_down_sync(0xFFFFFFFFu, sp, off);
        sn += __shfl_down_sync(0xFFFFFFFFu, sn, off);
    }
    __shared__ float wsp[8], wsn[8];
    int w = threadIdx.x >> 5;
    if ((threadIdx.x & 31) == 0) { wsp[w] = sp; wsn[w] = sn; }
    __syncthreads();
    if (threadIdx.x == 0) {
        float tp = 0.f, tn = 0.f;
#pragma unroll
        for (int ww = 0; ww < 8; ww++) { tp += wsp[ww]; tn += wsn[ww]; }
        float per = fmaxf(sqrtf(tp) - sqrtf(tn) + 0.3f, 0.f);
        g_loss[i]  = s_val ? per : 0.f;
        g_valid[i] = s_val;
    }
}

// ===================== kernel 4: final reduction =====================
__global__ void finalKernel(float* __restrict__ out, int B) {
    __shared__ float ssum[1024];
    __shared__ int   scnt[1024];
    float s = 0.f; int c = 0;
    for (int i = threadIdx.x; i < B; i += 1024) {
        s += g_loss[i];
        c += g_valid[i];
    }
    ssum[threadIdx.x] = s;
    scnt[threadIdx.x] = c;
    __syncthreads();
    for (int off = 512; off > 0; off >>= 1) {
        if (threadIdx.x < off) {
            ssum[threadIdx.x] += ssum[threadIdx.x + off];
            scnt[threadIdx.x] += scnt[threadIdx.x + off];
        }
        __syncthreads();
    }
    if (threadIdx.x == 0)
        out[0] = (scnt[0] > 0) ? ssum[0] / (float)scnt[0] : 0.f;
}

// ===================== launch =====================
extern "C" void kernel_launch(void* const* d_in, const int* in_sizes, int n_in,
                              void* d_out, int out_size) {
    const float* emb    = (const float*)d_in[0];
    const int*   labels = (const int*)d_in[1];
    float*       out    = (float*)d_out;
    int B = in_sizes[1];
    int D = in_sizes[0] / B;

    cudaFuncSetAttribute(distKernel, cudaFuncAttributeMaxDynamicSharedMemorySize, SMEM_TOTAL);

    convKernel<<<B / 8, 256>>>(emb, D);
    int nb = B / BM;
    int ntiles = nb * (nb + 1) / 2;
    distKernel<<<ntiles, 256, SMEM_TOTAL>>>(labels, B, D);
    lossKernel<<<B, 256>>>(emb, D, B);
    finalKernel<<<1, 1024>>>(out, B);
}

// round 12
// speedup vs baseline: 1.0960x; 1.0497x over previous
#include <cuda_runtime.h>
#include <cuda_bf16.h>
#include <cstdint>
#include <math.h>

// ===================== constants =====================
#define BMAX   4096
#define DMAX   2048
#define BM 128
#define BN 128
#define TBK 64                      // bf16 K per chunk = 128 bytes/row
#define STAGES 3
#define A_BYTES (BM*TBK*2)          // 16384
#define B_BYTES (BN*TBK*2)          // 16384
#define STAGE_BYTES (A_BYTES+B_BYTES)   // 32768
#define META_OFF (STAGES*STAGE_BYTES)   // 98304 (labels/sq, 2 KB)
#define SMEM_TOTAL (META_OFF + 2048)    // 100352 -> 2 CTAs/SM
#define NCHUNK (BMAX/BN)            // 32

#define POS_EMPTY 0ull
#define NEG_EMPTY 0xFFFFFFFFFFFFFFFFull

// ===================== device scratch =====================
__device__ __nv_bfloat16 g_ebf[(size_t)BMAX * DMAX];
__device__ float g_sq[BMAX];
__device__ unsigned long long g_pos[NCHUNK][BMAX];
__device__ unsigned long long g_neg[NCHUNK][BMAX];
__device__ int   g_valid[BMAX];
__device__ float g_loss[BMAX];

// ===================== helpers =====================
__device__ __forceinline__ uint32_t smem_u32(const void* p) {
    uint32_t a;
    asm("{ .reg .u64 t; cvta.to.shared.u64 t, %1; cvt.u32.u64 %0, t; }" : "=r"(a) : "l"(p));
    return a;
}
__device__ __forceinline__ void cpa16(uint32_t s, const void* g) {
    asm volatile("cp.async.cg.shared.global [%0], [%1], 16;" :: "r"(s), "l"(g));
}
#define CPA_COMMIT() asm volatile("cp.async.commit_group;" ::: "memory")
#define CPA_WAIT(N)  asm volatile("cp.async.wait_group %0;" :: "n"(N) : "memory")

__device__ __forceinline__ void ldsm4(uint32_t* r, uint32_t addr) {
    asm volatile("ldmatrix.sync.aligned.m8n8.x4.shared.b16 {%0,%1,%2,%3}, [%4];"
                 : "=r"(r[0]), "=r"(r[1]), "=r"(r[2]), "=r"(r[3]) : "r"(addr));
}
__device__ __forceinline__ void mma16816(float* c, const uint32_t* a, const uint32_t* b) {
    asm volatile(
        "mma.sync.aligned.m16n8k16.row.col.f32.bf16.bf16.f32 "
        "{%0,%1,%2,%3}, {%4,%5,%6,%7}, {%8,%9}, {%0,%1,%2,%3};"
        : "+f"(c[0]), "+f"(c[1]), "+f"(c[2]), "+f"(c[3])
        : "r"(a[0]), "r"(a[1]), "r"(a[2]), "r"(a[3]), "r"(b[0]), "r"(b[1]));
}

// packed selection keys: d2 >= 0 so float bits are order-preserving.
// pos (argmax, lowest index wins ties): key = (bits(d2)<<32) | (0xFFFFFFFF - j), take max
// neg (argmin, lowest index wins ties): key = (bits(d2)<<32) | j,                take min
__device__ __forceinline__ unsigned long long packPos(float d2, int j) {
    return ((unsigned long long)__float_as_uint(d2) << 32) |
           (unsigned long long)(0xFFFFFFFFu - (uint32_t)j);
}
__device__ __forceinline__ unsigned long long packNeg(float d2, int j) {
    return ((unsigned long long)__float_as_uint(d2) << 32) | (unsigned long long)(uint32_t)j;
}
__device__ __forceinline__ unsigned long long u64max(unsigned long long a, unsigned long long b) {
    return a > b ? a : b;
}
__device__ __forceinline__ unsigned long long u64min(unsigned long long a, unsigned long long b) {
    return a < b ? a : b;
}

// ===================== kernel 1: fp32 -> bf16 + row sumsq (warp-per-row) ==========
__global__ __launch_bounds__(256) void convKernel(const float* __restrict__ emb, int D) {
    const int warp = threadIdx.x >> 5;
    const int lane = threadIdx.x & 31;
    const int i = blockIdx.x * 8 + warp;
    const float4* row = reinterpret_cast<const float4*>(emb + (size_t)i * D);
    __nv_bfloat162* orow = reinterpret_cast<__nv_bfloat162*>(g_ebf + (size_t)i * D);

    float s = 0.f;
#pragma unroll
    for (int t = 0; t < 16; t++) {
        int k = lane + 32 * t;
        float4 v = row[k];
        s += v.x * v.x + v.y * v.y + v.z * v.z + v.w * v.w;
        __nv_bfloat162 h0, h1;
        h0.x = __float2bfloat16(v.x); h0.y = __float2bfloat16(v.y);
        h1.x = __float2bfloat16(v.z); h1.y = __float2bfloat16(v.w);
        orow[2 * k] = h0; orow[2 * k + 1] = h1;
    }
#pragma unroll
    for (int off = 16; off > 0; off >>= 1)
        s += __shfl_down_sync(0xFFFFFFFFu, s, off);
    if (lane == 0) g_sq[i] = s;
}

// ===================== kernel 2: bf16 HMMA GEMM (upper triangle), 64x64 warp tiles ==========
__device__ __forceinline__ void load_chunk(int tid, uint32_t sbase, int s,
                                           int iBase, int jBase, int c, int D) {
    uint32_t sA = sbase + s * STAGE_BYTES;
    uint32_t sB = sA + A_BYTES;
    int k0 = c * TBK;
    const char* gA = (const char*)(g_ebf + (size_t)iBase * D + k0);
    const char* gB = (const char*)(g_ebf + (size_t)jBase * D + k0);
#pragma unroll
    for (int t = 0; t < 8; t++) {
        int f = tid + t * 128;
        int row = f >> 3, c16 = f & 7;
        int colb = c16 * 16;
        uint32_t off = (uint32_t)(row * 128 + (colb ^ ((row & 7) << 4)));
        cpa16(sA + off, gA + (size_t)row * (size_t)(D * 2) + colb);
    }
#pragma unroll
    for (int t = 0; t < 8; t++) {
        int f = tid + t * 128;
        int row = f >> 3, c16 = f & 7;
        int colb = c16 * 16;
        uint32_t off = (uint32_t)(row * 128 + (colb ^ ((row & 7) << 4)));
        cpa16(sB + off, gB + (size_t)row * (size_t)(D * 2) + colb);
    }
    CPA_COMMIT();
}

__global__ __launch_bounds__(128, 2) void distKernel(const int* __restrict__ labels,
                                                     int B, int D) {
    extern __shared__ char sm[];
    uint32_t sbase = smem_u32(sm);

    const int tid  = threadIdx.x;
    const int wid  = tid >> 5;
    const int lane = tid & 31;
    const int warpM = wid & 1;       // 0..1 (64 rows each)
    const int warpN = wid >> 1;      // 0..1 (64 cols each)

    // decode upper-triangular tile (bi <= bj)
    const int nb = B / BM;           // 32
    int bi = 0, rem = blockIdx.x;
    while (rem >= nb - bi) { rem -= nb - bi; bi++; }
    const int bj = bi + rem;
    const int iBase = bi * BM;
    const int jBase = bj * BN;
    const bool diag = (bi == bj);

    int*   sLabJ = (int*)  (sm + META_OFF);
    float* sSqJ  = (float*)(sm + META_OFF + 512);
    int*   sLabI = (int*)  (sm + META_OFF + 1024);
    float* sSqI  = (float*)(sm + META_OFF + 1536);
    // selection-exchange buffers reuse stage-0 smem (epilogue only)
    unsigned long long* sRowP = (unsigned long long*)(sm);          // 128*2 u64 = 2KB
    unsigned long long* sRowN = (unsigned long long*)(sm + 2048);
    unsigned long long* sColP = (unsigned long long*)(sm + 4096);
    unsigned long long* sColN = (unsigned long long*)(sm + 6144);

    if (tid < 128) {
        sLabJ[tid] = labels[jBase + tid];
        sSqJ[tid]  = g_sq[jBase + tid];
        sLabI[tid] = labels[iBase + tid];
        sSqI[tid]  = g_sq[iBase + tid];
    }

    const int rowA_l = (lane & 7) + ((lane >> 3) & 1) * 8;
    const int colA_b = (lane >> 4) * 16;
    const int rowB_l = (lane & 7) + (lane >> 4) * 8;
    const int colB_b = ((lane >> 3) & 1) * 16;

    int aRow[4], bRow[4];
#pragma unroll
    for (int mf = 0; mf < 4; mf++) aRow[mf] = warpM * 64 + mf * 16 + rowA_l;
#pragma unroll
    for (int nf = 0; nf < 4; nf++) bRow[nf] = warpN * 64 + nf * 16 + rowB_l;

    float acc[4][8][4];
#pragma unroll
    for (int a = 0; a < 4; a++)
#pragma unroll
        for (int b = 0; b < 8; b++)
#pragma unroll
            for (int c = 0; c < 4; c++) acc[a][b][c] = 0.f;

    const int nch = D / TBK;     // 32

    load_chunk(tid, sbase, 0, iBase, jBase, 0, D);
    load_chunk(tid, sbase, 1, iBase, jBase, 1, D);

    for (int c = 0; c < nch; c++) {
        if (c == nch - 1) { CPA_WAIT(0); } else { CPA_WAIT(1); }
        __syncthreads();
        if (c + 2 < nch)
            load_chunk(tid, sbase, (c + 2) % STAGES, iBase, jBase, c + 2, D);

        uint32_t sA = sbase + (c % STAGES) * STAGE_BYTES;
        uint32_t sB = sA + A_BYTES;
#pragma unroll
        for (int ks = 0; ks < TBK / 16; ks++) {
            uint32_t aF[16], bF[16];
#pragma unroll
            for (int mf = 0; mf < 4; mf++) {
                int r = aRow[mf];
                ldsm4(aF + mf * 4, sA + r * 128 + ((ks * 32 + colA_b) ^ ((r & 7) << 4)));
            }
#pragma unroll
            for (int nf = 0; nf < 4; nf++) {
                int r = bRow[nf];
                ldsm4(bF + nf * 4, sB + r * 128 + ((ks * 32 + colB_b) ^ ((r & 7) << 4)));
            }
#pragma unroll
            for (int mf = 0; mf < 4; mf++)
#pragma unroll
                for (int n8 = 0; n8 < 8; n8++)
                    mma16816(acc[mf][n8], aF + mf * 4, bF + n8 * 2);
        }
    }
    __syncthreads();   // stage smem now reusable

    // ---- epilogue: d^2 + dual hard pos/neg selection (packed u64 keys) ----
    const int g = lane >> 2;
    const int q = lane & 3;

    unsigned long long ckP[16], ckN[16];
#pragma unroll
    for (int t = 0; t < 16; t++) { ckP[t] = POS_EMPTY; ckN[t] = NEG_EMPTY; }

#pragma unroll
    for (int mf = 0; mf < 4; mf++) {
#pragma unroll
        for (int h = 0; h < 2; h++) {
            int rl   = warpM * 64 + mf * 16 + h * 8 + g;
            int iRow = iBase + rl;
            float sqi = sSqI[rl];
            int   lab = sLabI[rl];
            unsigned long long pKey = POS_EMPTY, nKey = NEG_EMPTY;
#pragma unroll
            for (int t = 0; t < 16; t++) {
                int n8 = t >> 1, cc = t & 1;
                int jj = warpN * 64 + n8 * 8 + q * 2 + cc;
                int j  = jBase + jj;
                float d2 = fmaxf(sqi + sSqJ[jj] - 2.f * acc[mf][n8][h * 2 + cc], 0.f);
                if (sLabJ[jj] == lab) {
                    if (j != iRow) {
                        pKey  = u64max(pKey, packPos(d2, j));
                        ckP[t] = u64max(ckP[t], packPos(d2, iRow));
                    }
                } else {
                    nKey  = u64min(nKey, packNeg(d2, j));
                    ckN[t] = u64min(ckN[t], packNeg(d2, iRow));
                }
            }
#pragma unroll
            for (int off = 1; off <= 2; off <<= 1) {
                pKey = u64max(pKey, __shfl_xor_sync(0xFFFFFFFFu, pKey, off));
                nKey = u64min(nKey, __shfl_xor_sync(0xFFFFFFFFu, nKey, off));
            }
            if (q == 0) {
                sRowP[rl * 2 + warpN] = pKey;
                sRowN[rl * 2 + warpN] = nKey;
            }
        }
    }

    if (!diag) {
#pragma unroll
        for (int t = 0; t < 16; t++) {
#pragma unroll
            for (int off = 4; off <= 16; off <<= 1) {
                ckP[t] = u64max(ckP[t], __shfl_xor_sync(0xFFFFFFFFu, ckP[t], off));
                ckN[t] = u64min(ckN[t], __shfl_xor_sync(0xFFFFFFFFu, ckN[t], off));
            }
        }
        if (g == 0) {
#pragma unroll
            for (int t = 0; t < 16; t++) {
                int n8 = t >> 1, cc = t & 1;
                int jj = warpN * 64 + n8 * 8 + q * 2 + cc;
                sColP[jj * 2 + warpM] = ckP[t];
                sColN[jj * 2 + warpM] = ckN[t];
            }
        }
    }
    __syncthreads();

    if (tid < 128) {
        unsigned long long pKey = u64max(sRowP[tid * 2], sRowP[tid * 2 + 1]);
        unsigned long long nKey = u64min(sRowN[tid * 2], sRowN[tid * 2 + 1]);
        int iRow = iBase + tid;
        g_pos[bj][iRow] = pKey;
        g_neg[bj][iRow] = nKey;

        if (!diag) {
            unsigned long long cp = u64max(sColP[tid * 2], sColP[tid * 2 + 1]);
            unsigned long long cn = u64min(sColN[tid * 2], sColN[tid * 2 + 1]);
            int jRow = jBase + tid;
            g_pos[bi][jRow] = cp;
            g_neg[bi][jRow] = cn;
        }
    }
}

// ===================== kernel 3: fused merge + exact dp/dn loss =====================
__global__ __launch_bounds__(256) void lossKernel(const float* __restrict__ emb,
                                                  int D, int B) {
    int i = blockIdx.x;
    __shared__ int s_hp, s_hn, s_val;

    if (threadIdx.x < 32) {
        int c = threadIdx.x;    // NCHUNK == 32
        unsigned long long pKey = g_pos[c][i];
        unsigned long long nKey = g_neg[c][i];
#pragma unroll
        for (int off = 16; off > 0; off >>= 1) {
            pKey = u64max(pKey, __shfl_xor_sync(0xFFFFFFFFu, pKey, off));
            nKey = u64min(nKey, __shfl_xor_sync(0xFFFFFFFFu, nKey, off));
        }
        if (threadIdx.x == 0) {
            int hp = (int)(0xFFFFFFFFu - (uint32_t)pKey);
            int hn = (int)(uint32_t)nKey;
            int vp = (pKey != POS_EMPTY);
            int vn = (nKey != NEG_EMPTY);
            s_hp  = (vp && hp >= 0 && hp < B) ? hp : 0;
            s_hn  = (vn && hn >= 0 && hn < B) ? hn : 0;
            s_val = vp && vn;
        }
    }
    __syncthreads();

    int hp = s_hp, hn = s_hn;
    const float* a = emb + (size_t)i  * D;
    const float* p = emb + (size_t)hp * D;
    const float* n = emb + (size_t)hn * D;
    float sp = 0.f, sn = 0.f;
    for (int k = threadIdx.x * 4; k < D; k += blockDim.x * 4) {
        float4 va = *reinterpret_cast<const float4*>(a + k);
        float4 vp = *reinterpret_cast<const float4*>(p + k);
        float4 vn = *reinterpret_cast<const float4*>(n + k);
        float d;
        d = va.x - vp.x + 1e-6f; sp += d * d;
        d = va.y - vp.y + 1e-6f; sp += d * d;
        d = va.z - vp.z + 1e-6f; sp += d * d;
        d = va.w - vp.w + 1e-6f; sp += d * d;
        d = va.x - vn.x + 1e-6f; sn += d * d;
        d = va.y - vn.y + 1e-6f; sn += d * d;
        d = va.z - vn.z + 1e-6f; sn += d * d;
        d = va.w - vn.w + 1e-6f; sn += d * d;
    }
    for (int off = 16; off > 0; off >>= 1) {
        sp += __shfl_down_sync(0xFFFFFFFFu, sp, off);
        sn += __shfl_down_sync(0xFFFFFFFFu, sn, off);
    }
    __shared__ float wsp[8], wsn[8];
    int w = threadIdx.x >> 5;
    if ((threadIdx.x & 31) == 0) { wsp[w] = sp; wsn[w] = sn; }
    __syncthreads();
    if (threadIdx.x == 0) {
        float tp = 0.f, tn = 0.f;
#pragma unroll
        for (int ww = 0; ww < 8; ww++) { tp += wsp[ww]; tn += wsn[ww]; }
        float per = fmaxf(sqrtf(tp) - sqrtf(tn) + 0.3f, 0.f);
        g_loss[i]  = s_val ? per : 0.f;
        g_valid[i] = s_val;
    }
}

// ===================== kernel 4: final reduction =====================
__global__ void finalKernel(float* __restrict__ out, int B) {
    __shared__ float ssum[1024];
    __shared__ int   scnt[1024];
    float s = 0.f; int c = 0;
    for (int i = threadIdx.x; i < B; i += 1024) {
        s += g_loss[i];
        c += g_valid[i];
    }
    ssum[threadIdx.x] = s;
    scnt[threadIdx.x] = c;
    __syncthreads();
    for (int off = 512; off > 0; off >>= 1) {
        if (threadIdx.x < off) {
            ssum[threadIdx.x] += ssum[threadIdx.x + off];
            scnt[threadIdx.x] += scnt[threadIdx.x + off];
        }
        __syncthreads();
    }
    if (threadIdx.x == 0)
        out[0] = (scnt[0] > 0) ? ssum[0] / (float)scnt[0] : 0.f;
}

// ===================== launch =====================
extern "C" void kernel_launch(void* const* d_in, const int* in_sizes, int n_in,
                              void* d_out, int out_size) {
    const float* emb    = (const float*)d_in[0];
    const int*   labels = (const int*)d_in[1];
    float*       out    = (float*)d_out;
    int B = in_sizes[1];
    int D = in_sizes[0] / B;

    cudaFuncSetAttribute(distKernel, cudaFuncAttributeMaxDynamicSharedMemorySize, SMEM_TOTAL);

    convKernel<<<B / 8, 256>>>(emb, D);
    int nb = B / BM;
    int ntiles = nb * (nb + 1) / 2;
    distKernel<<<ntiles, 128, SMEM_TOTAL>>>(labels, B, D);
    lossKernel<<<B, 256>>>(emb, D, B);
    finalKernel<<<1, 1024>>>(out, B);
}